// round 13
// baseline (speedup 1.0000x reference)
#include <cuda_runtime.h>
#include <cuda_bf16.h>
#include <math.h>
#include <stdint.h>

#define DMODEL 1024
#define NHEADS 16
#define HDIM   64
#define BATCH  2
#define SEQ    2048
#define NELEM  (BATCH*SEQ*DMODEL)     // 4M
#define WELEM  (DMODEL*DMODEL)        // 1M

// ---------------- scratch (device globals; no allocation) ----------------
__device__ __nv_bfloat16 g_xh[NELEM],  g_xl[NELEM];      // x split
__device__ __nv_bfloat16 g_wh[4*WELEM], g_wl[4*WELEM];   // wq,wk,wv,wo split
__device__ __nv_bfloat16 g_qh[NELEM], g_ql[NELEM];       // (B,H,S,d), q pre-scaled 1/8
__device__ __nv_bfloat16 g_kh[NELEM], g_kl[NELEM];
__device__ __nv_bfloat16 g_vh[NELEM], g_vl[NELEM];
__device__ __nv_bfloat16 g_ah[NELEM], g_al[NELEM];       // attn out (B,S,D) split
__device__ float g_rope[SEQ*32*2];                       // [ss][f] -> (cos,sin)

// ---------------- helpers ----------------
__device__ __forceinline__ uint32_t smem_u32(const void* p) {
    uint32_t a;
    asm("{ .reg .u64 t; cvta.to.shared.u64 t, %1; cvt.u32.u64 %0, t; }" : "=r"(a) : "l"(p));
    return a;
}
__device__ __forceinline__ void ldsm4(uint32_t* r, uint32_t addr) {
    asm volatile("ldmatrix.sync.aligned.m8n8.x4.shared.b16 {%0,%1,%2,%3}, [%4];"
                 : "=r"(r[0]), "=r"(r[1]), "=r"(r[2]), "=r"(r[3]) : "r"(addr));
}
__device__ __forceinline__ void ldsm4t(uint32_t* r, uint32_t addr) {
    asm volatile("ldmatrix.sync.aligned.m8n8.x4.trans.shared.b16 {%0,%1,%2,%3}, [%4];"
                 : "=r"(r[0]), "=r"(r[1]), "=r"(r[2]), "=r"(r[3]) : "r"(addr));
}
// NOTE: non-volatile — pure register op, lets ptxas interleave independent mma
// and hide the ~24cyc accumulate latency across the 8-16 independent acc chains.
__device__ __forceinline__ void mma_bf16(float* d, const uint32_t* a, const uint32_t* b) {
    asm("mma.sync.aligned.m16n8k16.row.col.f32.bf16.bf16.f32 "
        "{%0,%1,%2,%3}, {%4,%5,%6,%7}, {%8,%9}, {%0,%1,%2,%3};"
        : "+f"(d[0]), "+f"(d[1]), "+f"(d[2]), "+f"(d[3])
        : "r"(a[0]), "r"(a[1]), "r"(a[2]), "r"(a[3]), "r"(b[0]), "r"(b[1]));
}
__device__ __forceinline__ void split2(float a, float b, uint32_t& hi, uint32_t& lo) {
    __nv_bfloat162 h = __floats2bfloat162_rn(a, b);
    hi = *(const uint32_t*)&h;
    __nv_bfloat162 l = __floats2bfloat162_rn(a - __bfloat162float(h.x),
                                             b - __bfloat162float(h.y));
    lo = *(const uint32_t*)&l;
}
__device__ __forceinline__ void cp16(uint32_t dst, const void* src) {
    asm volatile("cp.async.cg.shared.global [%0], [%1], 16;" :: "r"(dst), "l"(src));
}
#define CP_COMMIT() asm volatile("cp.async.commit_group;" ::: "memory")
#define CP_WAIT1()  asm volatile("cp.async.wait_group 1;" ::: "memory")
#define CP_WAIT0()  asm volatile("cp.async.wait_group 0;" ::: "memory")

// ---------------- kernel P: pre-split f32 -> bf16 hi/lo ----------------
__global__ void __launch_bounds__(256) presplit_kernel(
    const float* __restrict__ x,  const float* __restrict__ wq,
    const float* __restrict__ wk, const float* __restrict__ wv,
    const float* __restrict__ wo) {
    const int zz = blockIdx.y;
    const float* src; __nv_bfloat16 *dh, *dl; int n;
    if (zz == 0)      { src = x;  dh = g_xh; dl = g_xl; n = NELEM; }
    else              { src = (zz==1)?wq:(zz==2)?wk:(zz==3)?wv:wo;
                        dh = g_wh + (zz-1)*WELEM; dl = g_wl + (zz-1)*WELEM; n = WELEM; }
    int i = (blockIdx.x*256 + threadIdx.x)*4;
    if (i >= n) return;
    float4 v = *(const float4*)(src + i);
    uint32_t h0, l0, h1, l1;
    split2(v.x, v.y, h0, l0);
    split2(v.z, v.w, h1, l1);
    *(uint32_t*)&dh[i]   = h0; *(uint32_t*)&dh[i+2] = h1;
    *(uint32_t*)&dl[i]   = l0; *(uint32_t*)&dl[i+2] = l1;
}

// ---------------- split-bf16 GEMM: cp.async double-buffered ----------------
#define SROW   80
#define SBUF   (128*SROW)          // 10240
#define STAGE  (4*SBUF)            // 40960
#define GEMM_SMEM (2*STAGE)        // 81920

__device__ __forceinline__ void gemm_ps(const __nv_bfloat16* __restrict__ Ah,
                                        const __nv_bfloat16* __restrict__ Al,
                                        const __nv_bfloat16* __restrict__ Bh,
                                        const __nv_bfloat16* __restrict__ Bl,
                                        float (&d)[4][4][4]) {
    extern __shared__ __align__(16) char dsm[];
    const uint32_t sbase = smem_u32(dsm);
    const int tid  = threadIdx.x;
    const int lane = tid & 31, wid = tid >> 5;
    const int wm = wid & 1, wn = wid >> 1;
    const int r = tid >> 1, half = tid & 1;
    const int mi = lane >> 3, lr = lane & 7;

    #pragma unroll
    for (int i = 0; i < 4; i++)
        #pragma unroll
        for (int j = 0; j < 4; j++)
            #pragma unroll
            for (int q = 0; q < 4; q++) d[i][j][q] = 0.f;

    const __nv_bfloat16* pah = Ah + r*DMODEL + half*16;
    const __nv_bfloat16* pal = Al + r*DMODEL + half*16;
    const __nv_bfloat16* pbh = Bh + r*DMODEL + half*16;
    const __nv_bfloat16* pbl = Bl + r*DMODEL + half*16;
    const uint32_t dbase = sbase + r*SROW + half*32;

    const int NCH = DMODEL / 32;

    {
        cp16(dbase + 0*SBUF,      pah);  cp16(dbase + 0*SBUF + 16, pah + 8);
        cp16(dbase + 1*SBUF,      pal);  cp16(dbase + 1*SBUF + 16, pal + 8);
        cp16(dbase + 2*SBUF,      pbh);  cp16(dbase + 2*SBUF + 16, pbh + 8);
        cp16(dbase + 3*SBUF,      pbl);  cp16(dbase + 3*SBUF + 16, pbl + 8);
        CP_COMMIT();
    }

    for (int ch = 0; ch < NCH; ch++) {
        if (ch + 1 < NCH) {
            const uint32_t db = dbase + ((ch+1) & 1)*STAGE;
            const int ko = (ch+1)*32;
            cp16(db + 0*SBUF,      pah + ko);  cp16(db + 0*SBUF + 16, pah + ko + 8);
            cp16(db + 1*SBUF,      pal + ko);  cp16(db + 1*SBUF + 16, pal + ko + 8);
            cp16(db + 2*SBUF,      pbh + ko);  cp16(db + 2*SBUF + 16, pbh + ko + 8);
            cp16(db + 3*SBUF,      pbl + ko);  cp16(db + 3*SBUF + 16, pbl + ko + 8);
            CP_COMMIT();
            CP_WAIT1();
        } else {
            CP_WAIT0();
        }
        __syncthreads();

        const uint32_t sb = sbase + (ch & 1)*STAGE;
        #pragma unroll
        for (int st = 0; st < 2; st++) {
            uint32_t ahi[4][4], alo[4][4];
            #pragma unroll
            for (int i = 0; i < 4; i++) {
                int arow = wm*64 + i*16 + ((mi & 1) << 3) + lr;
                uint32_t aoff = (uint32_t)(arow*SROW + st*32 + ((mi >> 1) << 4));
                ldsm4(ahi[i], sb + 0*SBUF + aoff);
                ldsm4(alo[i], sb + 1*SBUF + aoff);
            }
            uint32_t bhi[2][4], blo[2][4];
            #pragma unroll
            for (int j2 = 0; j2 < 2; j2++) {
                int nrow = wn*32 + j2*16 + ((mi >> 1) << 3) + lr;
                uint32_t boff = (uint32_t)(nrow*SROW + st*32 + ((mi & 1) << 4));
                ldsm4(bhi[j2], sb + 2*SBUF + boff);
                ldsm4(blo[j2], sb + 3*SBUF + boff);
            }
            // pass-outermost: consecutive mma hit independent accumulators.
            // Per-accumulator order stays hh,hl,lh per chunk (bit-identical result).
            #pragma unroll
            for (int p = 0; p < 3; p++)
                #pragma unroll
                for (int i = 0; i < 4; i++)
                    #pragma unroll
                    for (int j = 0; j < 4; j++) {
                        const uint32_t* a  = (p == 2) ? alo[i] : ahi[i];
                        const uint32_t* bb = (p == 1) ? &blo[j >> 1][(j & 1)*2]
                                                      : &bhi[j >> 1][(j & 1)*2];
                        mma_bf16(d[i][j], a, bb);
                    }
        }
        __syncthreads();
    }
}

// ---------------- kernel 0: RoPE cos/sin table ----------------
__global__ void __launch_bounds__(256) rope_table_kernel() {
    int t = blockIdx.x * 256 + threadIdx.x;
    int f = t & 31, ss = t >> 5;
    const double lc = -0.28782313662425575;   // -ln(10000)/32
    float inv = (float)exp((double)f * lc);
    float ang = (float)ss * inv;
    double a = (double)ang;
    ((float2*)g_rope)[t] = make_float2((float)cos(a), (float)sin(a));
}

// ---------------- kernel 1: QKV projection + RoPE, writes hi/lo bf16 ----------------
__global__ void __launch_bounds__(256, 2) qkv_mma_kernel() {
    const int z  = blockIdx.z;
    const int m0 = blockIdx.y * 128;
    const int n0 = blockIdx.x * 128;
    __nv_bfloat16* oh = (z == 0) ? g_qh : (z == 1) ? g_kh : g_vh;
    __nv_bfloat16* ol = (z == 0) ? g_ql : (z == 1) ? g_kl : g_vl;

    float d[4][4][4];
    gemm_ps(g_xh + (size_t)m0*DMODEL, g_xl + (size_t)m0*DMODEL,
            g_wh + (size_t)z*WELEM + (size_t)n0*DMODEL,
            g_wl + (size_t)z*WELEM + (size_t)n0*DMODEL, d);

    const int lane = threadIdx.x & 31, wid = threadIdx.x >> 5;
    const int wm = wid & 1, wn = wid >> 1;

    #pragma unroll
    for (int i = 0; i < 4; i++) {
        #pragma unroll
        for (int rr = 0; rr < 2; rr++) {
            int m  = m0 + wm*64 + i*16 + rr*8 + (lane >> 2);
            int ss = m & (SEQ - 1), bb = m >> 11;
            #pragma unroll
            for (int j = 0; j < 4; j++) {
                int c = n0 + wn*32 + j*8 + 2*(lane & 3);
                float e = d[i][j][rr*2 + 0];
                float o = d[i][j][rr*2 + 1];
                if (z < 2) {
                    float2 t = ((const float2*)g_rope)[ss*32 + ((c & 63) >> 1)];
                    float e2 = e*t.x - o*t.y;
                    o = e*t.y + o*t.x;
                    e = e2;
                }
                if (z == 0) { e *= 0.125f; o *= 0.125f; }   // fold 1/sqrt(64) into q (exact)
                int head = c >> 6, jd = c & 63;
                size_t idx = (((size_t)(bb*NHEADS + head))*SEQ + ss)*HDIM + jd;
                uint32_t hw, lw;
                split2(e, o, hw, lw);
                *(uint32_t*)&oh[idx] = hw;
                *(uint32_t*)&ol[idx] = lw;
            }
        }
    }
}

// ---------------- kernel 3: output projection ----------------
__global__ void __launch_bounds__(256, 2) oproj_mma_kernel(float* __restrict__ out) {
    const int m0 = blockIdx.y * 128;
    const int n0 = blockIdx.x * 128;
    float d[4][4][4];
    gemm_ps(g_ah + (size_t)m0*DMODEL, g_al + (size_t)m0*DMODEL,
            g_wh + (size_t)3*WELEM + (size_t)n0*DMODEL,
            g_wl + (size_t)3*WELEM + (size_t)n0*DMODEL, d);

    const int lane = threadIdx.x & 31, wid = threadIdx.x >> 5;
    const int wm = wid & 1, wn = wid >> 1;
    #pragma unroll
    for (int i = 0; i < 4; i++)
        #pragma unroll
        for (int rr = 0; rr < 2; rr++) {
            int m = m0 + wm*64 + i*16 + rr*8 + (lane >> 2);
            #pragma unroll
            for (int j = 0; j < 4; j++) {
                int c = n0 + wn*32 + j*8 + 2*(lane & 3);
                *(float2*)&out[(size_t)m*DMODEL + c] =
                    make_float2(d[i][j][rr*2 + 0], d[i][j][rr*2 + 1]);
            }
        }
}

// ---------------- kernel 2: causal flash attention (split-bf16 mma, cp.async) --------
// Q hi/lo staged into stage-0's region, hoisted to registers, then the region is
// reused as K/V stage buffer 0 (smem union). Natural regs, 1 CTA/SM (occ2 proven flat).
#define AT_STRIDE 144
#define STG_K  (64*AT_STRIDE)             // 9216 per buffer (KHI,KLO,VHI,VLO)
#define STG_SZ (4*STG_K)                  // 36864 per stage
#define SM_QHI 0                           // overlaps stage 0
#define SM_QLO (128*AT_STRIDE)             // 18432 (still inside stage-0 region)
#define ATTN_MMA_SMEM (2*STG_SZ)           // 73728 B

__device__ __forceinline__ void attn_issue(uint32_t sb,
        const __nv_bfloat16* kh, const __nv_bfloat16* kl,
        const __nv_bfloat16* vh, const __nv_bfloat16* vl,
        int kb, int tid) {
    const int r = tid >> 2, q4 = tid & 3;
    const size_t g = (size_t)(kb*64 + r)*HDIM + q4*16;
    const uint32_t d = sb + r*AT_STRIDE + q4*32;
    cp16(d + 0*STG_K,      kh + g); cp16(d + 0*STG_K + 16, kh + g + 8);
    cp16(d + 1*STG_K,      kl + g); cp16(d + 1*STG_K + 16, kl + g + 8);
    cp16(d + 2*STG_K,      vh + g); cp16(d + 2*STG_K + 16, vh + g + 8);
    cp16(d + 3*STG_K,      vl + g); cp16(d + 3*STG_K + 16, vl + g + 8);
}

__global__ void __launch_bounds__(256) attn_mma_kernel() {
    extern __shared__ __align__(16) char smc[];
    const uint32_t sbase = smem_u32(smc);
    const int tid = threadIdx.x, lane = tid & 31, w = tid >> 5;
    const int qb = (int)gridDim.x - 1 - (int)blockIdx.x;   // long blocks first
    const int bh = blockIdx.y;
    const int mi = lane >> 3, lr = lane & 7;

    const size_t hb = (size_t)bh*SEQ*HDIM;
    const __nv_bfloat16* kh_g = g_kh + hb;
    const __nv_bfloat16* kl_g = g_kl + hb;
    const __nv_bfloat16* vh_g = g_vh + hb;
    const __nv_bfloat16* vl_g = g_vl + hb;

    const int nkv = 2*(qb + 1);

    // ---- stage Q hi/lo (already scaled by 1/8) into the stage-0 region ----
    {
        int r = tid >> 1, half = tid & 1;
        const __nv_bfloat16* qh = g_qh + hb + (size_t)(qb*128 + r)*HDIM + half*32;
        const __nv_bfloat16* ql = g_ql + hb + (size_t)(qb*128 + r)*HDIM + half*32;
        char* ph = smc + SM_QHI + r*AT_STRIDE + half*64;
        char* pl = smc + SM_QLO + r*AT_STRIDE + half*64;
        #pragma unroll
        for (int q = 0; q < 4; q++) {
            *(uint4*)(ph + q*16) = *(const uint4*)(qh + q*8);
            *(uint4*)(pl + q*16) = *(const uint4*)(ql + q*8);
        }
    }
    __syncthreads();

    // ---- hoist Q A-fragments ----
    uint32_t qhi[4][4], qlo[4][4];
    {
        int arow = w*16 + ((mi & 1) << 3) + lr;
        #pragma unroll
        for (int kk = 0; kk < 4; kk++) {
            uint32_t aoff = (uint32_t)(arow*AT_STRIDE + kk*32 + ((mi >> 1) << 4));
            ldsm4(qhi[kk], sbase + SM_QHI + aoff);
            ldsm4(qlo[kk], sbase + SM_QLO + aoff);
        }
    }
    __syncthreads();   // all warps done reading Q smem before stage-0 reuse

    // prefetch kv block 0 into stage 0 (reusing the Q region)
    attn_issue(sbase, kh_g, kl_g, vh_g, vl_g, 0, tid);
    CP_COMMIT();

    float o[8][4];
    #pragma unroll
    for (int j = 0; j < 8; j++) { o[j][0]=o[j][1]=o[j][2]=o[j][3]=0.f; }
    float m0 = -INFINITY, m1 = -INFINITY, l0 = 0.f, l1 = 0.f;

    for (int kb = 0; kb < nkv; kb++) {
        if (kb + 1 < nkv) {
            attn_issue(sbase + ((kb+1) & 1)*STG_SZ,
                       kh_g, kl_g, vh_g, vl_g, kb + 1, tid);
            CP_COMMIT();
            CP_WAIT1();
        } else {
            CP_WAIT0();
        }
        __syncthreads();

        const uint32_t sb = sbase + (kb & 1)*STG_SZ;

        // ---- S = (Q/8) K^T, 3-pass split, pass-outermost over 8 independent accs ----
        float s[8][4];
        #pragma unroll
        for (int j = 0; j < 8; j++) { s[j][0]=s[j][1]=s[j][2]=s[j][3]=0.f; }
        #pragma unroll
        for (int kk = 0; kk < 4; kk++) {
            uint32_t kbh[4][4], kbl[4][4];
            #pragma unroll
            for (int j2 = 0; j2 < 4; j2++) {
                int nrow = j2*16 + ((mi >> 1) << 3) + lr;
                uint32_t boff = (uint32_t)(nrow*AT_STRIDE + kk*32 + ((mi & 1) << 4));
                ldsm4(kbh[j2], sb + 0*STG_K + boff);
                ldsm4(kbl[j2], sb + 1*STG_K + boff);
            }
            #pragma unroll
            for (int p = 0; p < 3; p++)
                #pragma unroll
                for (int j = 0; j < 8; j++) {
                    const uint32_t* a  = (p == 2) ? qlo[kk] : qhi[kk];
                    const uint32_t* bb = (p == 1) ? &kbl[j >> 1][(j & 1)*2]
                                                  : &kbh[j >> 1][(j & 1)*2];
                    mma_bf16(s[j], a, bb);
                }
        }

        // ---- causal mask (diagonal band only) ----
        if (kb >= 2*qb) {
            int r0 = qb*128 + w*16 + (lane >> 2);
            int c0 = kb*64 + 2*(lane & 3);
            #pragma unroll
            for (int j = 0; j < 8; j++) {
                int cg = c0 + j*8;
                if (cg     > r0)     s[j][0] = -1e30f;
                if (cg + 1 > r0)     s[j][1] = -1e30f;
                if (cg     > r0 + 8) s[j][2] = -1e30f;
                if (cg + 1 > r0 + 8) s[j][3] = -1e30f;
            }
        }

        // ---- online softmax ----
        float mx0 = -1e30f, mx1 = -1e30f;
        #pragma unroll
        for (int j = 0; j < 8; j++) {
            mx0 = fmaxf(mx0, fmaxf(s[j][0], s[j][1]));
            mx1 = fmaxf(mx1, fmaxf(s[j][2], s[j][3]));
        }
        mx0 = fmaxf(mx0, __shfl_xor_sync(0xffffffffu, mx0, 1));
        mx0 = fmaxf(mx0, __shfl_xor_sync(0xffffffffu, mx0, 2));
        mx1 = fmaxf(mx1, __shfl_xor_sync(0xffffffffu, mx1, 1));
        mx1 = fmaxf(mx1, __shfl_xor_sync(0xffffffffu, mx1, 2));
        float mn0 = fmaxf(m0, mx0), mn1 = fmaxf(m1, mx1);
        float cf0 = __expf(m0 - mn0), cf1 = __expf(m1 - mn1);
        m0 = mn0; m1 = mn1;
        float rs0 = 0.f, rs1 = 0.f;
        #pragma unroll
        for (int j = 0; j < 8; j++) {
            s[j][0] = __expf(s[j][0] - mn0); rs0 += s[j][0];
            s[j][1] = __expf(s[j][1] - mn0); rs0 += s[j][1];
            s[j][2] = __expf(s[j][2] - mn1); rs1 += s[j][2];
            s[j][3] = __expf(s[j][3] - mn1); rs1 += s[j][3];
        }
        rs0 += __shfl_xor_sync(0xffffffffu, rs0, 1);
        rs0 += __shfl_xor_sync(0xffffffffu, rs0, 2);
        rs1 += __shfl_xor_sync(0xffffffffu, rs1, 1);
        rs1 += __shfl_xor_sync(0xffffffffu, rs1, 2);
        l0 = l0*cf0 + rs0;
        l1 = l1*cf1 + rs1;
        #pragma unroll
        for (int j = 0; j < 8; j++) {
            o[j][0] *= cf0; o[j][1] *= cf0;
            o[j][2] *= cf1; o[j][3] *= cf1;
        }

        // ---- O += P V  (V via ldmatrix.trans; pass-outermost over 8 accs) ----
        #pragma unroll
        for (int kk = 0; kk < 4; kk++) {
            uint32_t ahi[4], alo[4];
            split2(s[2*kk][0],   s[2*kk][1],   ahi[0], alo[0]);
            split2(s[2*kk][2],   s[2*kk][3],   ahi[1], alo[1]);
            split2(s[2*kk+1][0], s[2*kk+1][1], ahi[2], alo[2]);
            split2(s[2*kk+1][2], s[2*kk+1][3], ahi[3], alo[3]);
            uint32_t vbh[4][4], vbl[4][4];
            #pragma unroll
            for (int j2 = 0; j2 < 4; j2++) {
                int vrow = kk*16 + ((mi & 1) << 3) + lr;                 // kv index
                uint32_t boff = (uint32_t)(vrow*AT_STRIDE +
                                           (j2*16 + ((mi >> 1) << 3))*2); // d col bytes
                ldsm4t(vbh[j2], sb + 2*STG_K + boff);
                ldsm4t(vbl[j2], sb + 3*STG_K + boff);
            }
            #pragma unroll
            for (int p = 0; p < 3; p++)
                #pragma unroll
                for (int j = 0; j < 8; j++) {
                    const uint32_t* a  = (p == 2) ? alo : ahi;
                    const uint32_t* bb = (p == 1) ? &vbl[j >> 1][(j & 1)*2]
                                                  : &vbh[j >> 1][(j & 1)*2];
                    mma_bf16(o[j], a, bb);
                }
        }
        __syncthreads();   // all warps done reading stage kb&1 before it is re-filled
    }

    // ---- normalize + write (B,S,D) as bf16 hi/lo for oproj ----
    const int b = bh >> 4, h = bh & 15;
    const int s0 = qb*128 + w*16 + (lane >> 2);
    float i0 = 1.f / l0, i1 = 1.f / l1;
    #pragma unroll
    for (int j = 0; j < 8; j++) {
        int c = h*HDIM + j*8 + 2*(lane & 3);
        uint32_t hw, lw;
        size_t idx0 = ((size_t)b*SEQ + s0)*DMODEL + c;
        split2(o[j][0]*i0, o[j][1]*i0, hw, lw);
        *(uint32_t*)&g_ah[idx0] = hw;
        *(uint32_t*)&g_al[idx0] = lw;
        size_t idx1 = ((size_t)b*SEQ + s0 + 8)*DMODEL + c;
        split2(o[j][2]*i1, o[j][3]*i1, hw, lw);
        *(uint32_t*)&g_ah[idx1] = hw;
        *(uint32_t*)&g_al[idx1] = lw;
    }
}

// ---------------- launch ----------------
extern "C" void kernel_launch(void* const* d_in, const int* in_sizes, int n_in,
                              void* d_out, int out_size) {
    (void)in_sizes; (void)n_in; (void)out_size;
    const float* x  = (const float*)d_in[0];
    const float* wq = (const float*)d_in[1];
    const float* wk = (const float*)d_in[2];
    const float* wv = (const float*)d_in[3];
    const float* wo = (const float*)d_in[4];
    float* out = (float*)d_out;

    static bool attr_set = false;
    if (!attr_set) {
        cudaFuncSetAttribute(qkv_mma_kernel,  cudaFuncAttributeMaxDynamicSharedMemorySize, GEMM_SMEM);
        cudaFuncSetAttribute(oproj_mma_kernel, cudaFuncAttributeMaxDynamicSharedMemorySize, GEMM_SMEM);
        cudaFuncSetAttribute(attn_mma_kernel, cudaFuncAttributeMaxDynamicSharedMemorySize, ATTN_MMA_SMEM);
        attr_set = true;
    }

    presplit_kernel<<<dim3(NELEM/1024, 5), 256>>>(x, wq, wk, wv, wo);
    rope_table_kernel<<<SEQ*32/256, 256>>>();
    qkv_mma_kernel<<<dim3(8, 32, 3), 256, GEMM_SMEM>>>();
    attn_mma_kernel<<<dim3(16, 32), 256, ATTN_MMA_SMEM>>>();
    oproj_mma_kernel<<<dim3(8, 32), 256, GEMM_SMEM>>>(out);
}

// round 14
// speedup vs baseline: 1.3770x; 1.3770x over previous
#include <cuda_runtime.h>
#include <cuda_fp16.h>
#include <math.h>
#include <stdint.h>

#define DMODEL 1024
#define NHEADS 16
#define HDIM   64
#define BATCH  2
#define SEQ    2048
#define NELEM  (BATCH*SEQ*DMODEL)     // 4M
#define WELEM  (DMODEL*DMODEL)        // 1M

// ---------------- scratch (device globals; no allocation) ----------------
// fp16 split-2: only the A-side of each GEMM keeps a residual (lo); B-side is hi-only.
__device__ __half g_xh[NELEM], g_xl[NELEM];      // x hi/lo
__device__ __half g_wh[4*WELEM];                 // wq,wk,wv,wo hi only
__device__ __half g_qh[NELEM], g_ql[NELEM];      // q (B,H,S,d) hi/lo, pre-scaled 1/8
__device__ __half g_kh[NELEM];                   // k hi only (B-side of QK^T)
__device__ __half g_vh[NELEM];                   // v hi only (B-side of P*V)
__device__ __half g_ah[NELEM], g_al[NELEM];      // attn out (B,S,D) hi/lo
__device__ float g_rope[SEQ*32*2];               // [ss][f] -> (cos,sin)

// ---------------- helpers ----------------
__device__ __forceinline__ uint32_t smem_u32(const void* p) {
    uint32_t a;
    asm("{ .reg .u64 t; cvta.to.shared.u64 t, %1; cvt.u32.u64 %0, t; }" : "=r"(a) : "l"(p));
    return a;
}
__device__ __forceinline__ void ldsm4(uint32_t* r, uint32_t addr) {
    asm volatile("ldmatrix.sync.aligned.m8n8.x4.shared.b16 {%0,%1,%2,%3}, [%4];"
                 : "=r"(r[0]), "=r"(r[1]), "=r"(r[2]), "=r"(r[3]) : "r"(addr));
}
__device__ __forceinline__ void ldsm4t(uint32_t* r, uint32_t addr) {
    asm volatile("ldmatrix.sync.aligned.m8n8.x4.trans.shared.b16 {%0,%1,%2,%3}, [%4];"
                 : "=r"(r[0]), "=r"(r[1]), "=r"(r[2]), "=r"(r[3]) : "r"(addr));
}
__device__ __forceinline__ void mma_f16(float* d, const uint32_t* a, const uint32_t* b) {
    asm("mma.sync.aligned.m16n8k16.row.col.f32.f16.f16.f32 "
        "{%0,%1,%2,%3}, {%4,%5,%6,%7}, {%8,%9}, {%0,%1,%2,%3};"
        : "+f"(d[0]), "+f"(d[1]), "+f"(d[2]), "+f"(d[3])
        : "r"(a[0]), "r"(a[1]), "r"(a[2]), "r"(a[3]), "r"(b[0]), "r"(b[1]));
}
// split pair of floats into fp16 hi + fp16 residual (packed half2 words)
__device__ __forceinline__ void split2h(float a, float b, uint32_t& hi, uint32_t& lo) {
    __half2 h = __floats2half2_rn(a, b);
    hi = *(const uint32_t*)&h;
    __half2 l = __floats2half2_rn(a - __half2float(h.x), b - __half2float(h.y));
    lo = *(const uint32_t*)&l;
}
__device__ __forceinline__ uint32_t pack2h(float a, float b) {
    __half2 h = __floats2half2_rn(a, b);
    return *(const uint32_t*)&h;
}
__device__ __forceinline__ void cp16(uint32_t dst, const void* src) {
    asm volatile("cp.async.cg.shared.global [%0], [%1], 16;" :: "r"(dst), "l"(src));
}
#define CP_COMMIT() asm volatile("cp.async.commit_group;" ::: "memory")
#define CP_WAIT1()  asm volatile("cp.async.wait_group 1;" ::: "memory")
#define CP_WAIT0()  asm volatile("cp.async.wait_group 0;" ::: "memory")

// ---------------- kernel P: pre-split ----------------
__global__ void __launch_bounds__(256) presplit_kernel(
    const float* __restrict__ x,  const float* __restrict__ wq,
    const float* __restrict__ wk, const float* __restrict__ wv,
    const float* __restrict__ wo) {
    const int zz = blockIdx.y;
    int i = (blockIdx.x*256 + threadIdx.x)*4;
    if (zz == 0) {
        if (i >= NELEM) return;
        float4 v = *(const float4*)(x + i);
        uint32_t h0, l0, h1, l1;
        split2h(v.x, v.y, h0, l0);
        split2h(v.z, v.w, h1, l1);
        *(uint32_t*)&g_xh[i] = h0; *(uint32_t*)&g_xh[i+2] = h1;
        *(uint32_t*)&g_xl[i] = l0; *(uint32_t*)&g_xl[i+2] = l1;
    } else {
        if (i >= WELEM) return;
        const float* src = (zz==1)?wq:(zz==2)?wk:(zz==3)?wv:wo;
        float4 v = *(const float4*)(src + i);
        __half* dh = g_wh + (zz-1)*WELEM;
        *(uint32_t*)&dh[i]   = pack2h(v.x, v.y);
        *(uint32_t*)&dh[i+2] = pack2h(v.z, v.w);
    }
}

// ---------------- fp16 split-2 GEMM: cp.async double-buffered ----------------
// smem: 2 stages x 3 buffers [128 rows x (64B data + 16B pad)]: AHI, ALO, BHI
#define SROW   80
#define SBUF   (128*SROW)          // 10240
#define STAGE  (3*SBUF)            // 30720
#define GEMM_SMEM (2*STAGE)        // 61440

__device__ __forceinline__ void gemm_ps(const __half* __restrict__ Ah,
                                        const __half* __restrict__ Al,
                                        const __half* __restrict__ Bh,
                                        float (&d)[4][4][4]) {
    extern __shared__ __align__(16) char dsm[];
    const uint32_t sbase = smem_u32(dsm);
    const int tid  = threadIdx.x;
    const int lane = tid & 31, wid = tid >> 5;
    const int wm = wid & 1, wn = wid >> 1;
    const int r = tid >> 1, half = tid & 1;
    const int mi = lane >> 3, lr = lane & 7;

    #pragma unroll
    for (int i = 0; i < 4; i++)
        #pragma unroll
        for (int j = 0; j < 4; j++)
            #pragma unroll
            for (int q = 0; q < 4; q++) d[i][j][q] = 0.f;

    const __half* pah = Ah + r*DMODEL + half*16;
    const __half* pal = Al + r*DMODEL + half*16;
    const __half* pbh = Bh + r*DMODEL + half*16;
    const uint32_t dbase = sbase + r*SROW + half*32;

    const int NCH = DMODEL / 32;

    {
        cp16(dbase + 0*SBUF, pah);  cp16(dbase + 0*SBUF + 16, pah + 8);
        cp16(dbase + 1*SBUF, pal);  cp16(dbase + 1*SBUF + 16, pal + 8);
        cp16(dbase + 2*SBUF, pbh);  cp16(dbase + 2*SBUF + 16, pbh + 8);
        CP_COMMIT();
    }

    for (int ch = 0; ch < NCH; ch++) {
        if (ch + 1 < NCH) {
            const uint32_t db = dbase + ((ch+1) & 1)*STAGE;
            const int ko = (ch+1)*32;
            cp16(db + 0*SBUF, pah + ko);  cp16(db + 0*SBUF + 16, pah + ko + 8);
            cp16(db + 1*SBUF, pal + ko);  cp16(db + 1*SBUF + 16, pal + ko + 8);
            cp16(db + 2*SBUF, pbh + ko);  cp16(db + 2*SBUF + 16, pbh + ko + 8);
            CP_COMMIT();
            CP_WAIT1();
        } else {
            CP_WAIT0();
        }
        __syncthreads();

        const uint32_t sb = sbase + (ch & 1)*STAGE;
        #pragma unroll
        for (int st = 0; st < 2; st++) {
            uint32_t ahi[4][4], alo[4][4];
            #pragma unroll
            for (int i = 0; i < 4; i++) {
                int arow = wm*64 + i*16 + ((mi & 1) << 3) + lr;
                uint32_t aoff = (uint32_t)(arow*SROW + st*32 + ((mi >> 1) << 4));
                ldsm4(ahi[i], sb + 0*SBUF + aoff);
                ldsm4(alo[i], sb + 1*SBUF + aoff);
            }
            uint32_t bhi[2][4];
            #pragma unroll
            for (int j2 = 0; j2 < 2; j2++) {
                int nrow = wn*32 + j2*16 + ((mi >> 1) << 3) + lr;
                uint32_t boff = (uint32_t)(nrow*SROW + st*32 + ((mi & 1) << 4));
                ldsm4(bhi[j2], sb + 2*SBUF + boff);
            }
            // 2 passes: (a_hi + a_lo) * b_hi; per-acc order hi then lo.
            #pragma unroll
            for (int p = 0; p < 2; p++)
                #pragma unroll
                for (int i = 0; i < 4; i++)
                    #pragma unroll
                    for (int j = 0; j < 4; j++)
                        mma_f16(d[i][j], (p == 0) ? ahi[i] : alo[i],
                                &bhi[j >> 1][(j & 1)*2]);
        }
        __syncthreads();
    }
}

// ---------------- kernel 0: RoPE cos/sin table ----------------
__global__ void __launch_bounds__(256) rope_table_kernel() {
    int t = blockIdx.x * 256 + threadIdx.x;
    int f = t & 31, ss = t >> 5;
    const double lc = -0.28782313662425575;   // -ln(10000)/32
    float inv = (float)exp((double)f * lc);
    float ang = (float)ss * inv;
    double a = (double)ang;
    ((float2*)g_rope)[t] = make_float2((float)cos(a), (float)sin(a));
}

// ---------------- kernel 1: QKV projection + RoPE ----------------
__global__ void __launch_bounds__(256, 2) qkv_mma_kernel() {
    const int z  = blockIdx.z;
    const int m0 = blockIdx.y * 128;
    const int n0 = blockIdx.x * 128;

    float d[4][4][4];
    gemm_ps(g_xh + (size_t)m0*DMODEL, g_xl + (size_t)m0*DMODEL,
            g_wh + (size_t)z*WELEM + (size_t)n0*DMODEL, d);

    const int lane = threadIdx.x & 31, wid = threadIdx.x >> 5;
    const int wm = wid & 1, wn = wid >> 1;

    #pragma unroll
    for (int i = 0; i < 4; i++) {
        #pragma unroll
        for (int rr = 0; rr < 2; rr++) {
            int m  = m0 + wm*64 + i*16 + rr*8 + (lane >> 2);
            int ss = m & (SEQ - 1), bb = m >> 11;
            #pragma unroll
            for (int j = 0; j < 4; j++) {
                int c = n0 + wn*32 + j*8 + 2*(lane & 3);
                float e = d[i][j][rr*2 + 0];
                float o = d[i][j][rr*2 + 1];
                if (z < 2) {
                    float2 t = ((const float2*)g_rope)[ss*32 + ((c & 63) >> 1)];
                    float e2 = e*t.x - o*t.y;
                    o = e*t.y + o*t.x;
                    e = e2;
                }
                int head = c >> 6, jd = c & 63;
                size_t idx = (((size_t)(bb*NHEADS + head))*SEQ + ss)*HDIM + jd;
                if (z == 0) {
                    e *= 0.125f; o *= 0.125f;     // fold 1/sqrt(64), exact
                    uint32_t hw, lw;
                    split2h(e, o, hw, lw);
                    *(uint32_t*)&g_qh[idx] = hw;
                    *(uint32_t*)&g_ql[idx] = lw;
                } else if (z == 1) {
                    *(uint32_t*)&g_kh[idx] = pack2h(e, o);
                } else {
                    *(uint32_t*)&g_vh[idx] = pack2h(e, o);
                }
            }
        }
    }
}

// ---------------- kernel 3: output projection ----------------
__global__ void __launch_bounds__(256, 2) oproj_mma_kernel(float* __restrict__ out) {
    const int m0 = blockIdx.y * 128;
    const int n0 = blockIdx.x * 128;
    float d[4][4][4];
    gemm_ps(g_ah + (size_t)m0*DMODEL, g_al + (size_t)m0*DMODEL,
            g_wh + (size_t)3*WELEM + (size_t)n0*DMODEL, d);

    const int lane = threadIdx.x & 31, wid = threadIdx.x >> 5;
    const int wm = wid & 1, wn = wid >> 1;
    #pragma unroll
    for (int i = 0; i < 4; i++)
        #pragma unroll
        for (int rr = 0; rr < 2; rr++) {
            int m = m0 + wm*64 + i*16 + rr*8 + (lane >> 2);
            #pragma unroll
            for (int j = 0; j < 4; j++) {
                int c = n0 + wn*32 + j*8 + 2*(lane & 3);
                *(float2*)&out[(size_t)m*DMODEL + c] =
                    make_float2(d[i][j][rr*2 + 0], d[i][j][rr*2 + 1]);
            }
        }
}

// ---------------- kernel 2: causal flash attention (fp16 split-2 mma) ----------------
// Q hi/lo resident in registers after prologue; K/V staged HI-ONLY, double-buffered.
#define AT_STRIDE 144
#define STG_K  (64*AT_STRIDE)             // 9216 per buffer (KHI, VHI)
#define STG_SZ (2*STG_K)                  // 18432 per stage
#define SM_QHI 0                           // prologue-only; overlaps stage 0
#define SM_QLO STG_SZ                      // overlaps stage 1
#define ATTN_MMA_SMEM (2*STG_SZ)           // 36864 B

__device__ __forceinline__ void attn_issue(uint32_t sb,
        const __half* kh, const __half* vh, int kb, int tid) {
    const int r = tid >> 2, q4 = tid & 3;
    const size_t g = (size_t)(kb*64 + r)*HDIM + q4*16;
    const uint32_t d = sb + r*AT_STRIDE + q4*32;
    cp16(d + 0*STG_K, kh + g); cp16(d + 0*STG_K + 16, kh + g + 8);
    cp16(d + 1*STG_K, vh + g); cp16(d + 1*STG_K + 16, vh + g + 8);
}

__global__ void __launch_bounds__(256) attn_mma_kernel() {
    extern __shared__ __align__(16) char smc[];
    const uint32_t sbase = smem_u32(smc);
    const int tid = threadIdx.x, lane = tid & 31, w = tid >> 5;
    const int qb = (int)gridDim.x - 1 - (int)blockIdx.x;   // long blocks first
    const int bh = blockIdx.y;
    const int mi = lane >> 3, lr = lane & 7;

    const size_t hb = (size_t)bh*SEQ*HDIM;
    const __half* kh_g = g_kh + hb;
    const __half* vh_g = g_vh + hb;

    const int nkv = 2*(qb + 1);

    // ---- stage Q hi/lo into the stage regions (prologue only) ----
    {
        int r = tid >> 1, half = tid & 1;
        const __half* qh = g_qh + hb + (size_t)(qb*128 + r)*HDIM + half*32;
        const __half* ql = g_ql + hb + (size_t)(qb*128 + r)*HDIM + half*32;
        char* ph = smc + SM_QHI + r*AT_STRIDE + half*64;
        char* pl = smc + SM_QLO + r*AT_STRIDE + half*64;
        #pragma unroll
        for (int q = 0; q < 4; q++) {
            *(uint4*)(ph + q*16) = *(const uint4*)(qh + q*8);
            *(uint4*)(pl + q*16) = *(const uint4*)(ql + q*8);
        }
    }
    __syncthreads();

    // ---- hoist Q A-fragments ----
    uint32_t qhi[4][4], qlo[4][4];
    {
        int arow = w*16 + ((mi & 1) << 3) + lr;
        #pragma unroll
        for (int kk = 0; kk < 4; kk++) {
            uint32_t aoff = (uint32_t)(arow*AT_STRIDE + kk*32 + ((mi >> 1) << 4));
            ldsm4(qhi[kk], sbase + SM_QHI + aoff);
            ldsm4(qlo[kk], sbase + SM_QLO + aoff);
        }
    }
    __syncthreads();   // all warps done with Q smem before stage reuse

    // prefetch kv block 0 into stage 0
    attn_issue(sbase, kh_g, vh_g, 0, tid);
    CP_COMMIT();

    float o[8][4];
    #pragma unroll
    for (int j = 0; j < 8; j++) { o[j][0]=o[j][1]=o[j][2]=o[j][3]=0.f; }
    float m0 = -INFINITY, m1 = -INFINITY, l0 = 0.f, l1 = 0.f;

    for (int kb = 0; kb < nkv; kb++) {
        if (kb + 1 < nkv) {
            attn_issue(sbase + ((kb+1) & 1)*STG_SZ, kh_g, vh_g, kb + 1, tid);
            CP_COMMIT();
            CP_WAIT1();
        } else {
            CP_WAIT0();
        }
        __syncthreads();

        const uint32_t sb = sbase + (kb & 1)*STG_SZ;

        // ---- S = (Q/8) K^T, 2-pass: (q_hi + q_lo) * k_hi ----
        float s[8][4];
        #pragma unroll
        for (int j = 0; j < 8; j++) { s[j][0]=s[j][1]=s[j][2]=s[j][3]=0.f; }
        #pragma unroll
        for (int kk = 0; kk < 4; kk++) {
            uint32_t kbh[4][4];
            #pragma unroll
            for (int j2 = 0; j2 < 4; j2++) {
                int nrow = j2*16 + ((mi >> 1) << 3) + lr;
                uint32_t boff = (uint32_t)(nrow*AT_STRIDE + kk*32 + ((mi & 1) << 4));
                ldsm4(kbh[j2], sb + 0*STG_K + boff);
            }
            #pragma unroll
            for (int p = 0; p < 2; p++)
                #pragma unroll
                for (int j = 0; j < 8; j++)
                    mma_f16(s[j], (p == 0) ? qhi[kk] : qlo[kk],
                            &kbh[j >> 1][(j & 1)*2]);
        }

        // ---- causal mask (diagonal band only) ----
        if (kb >= 2*qb) {
            int r0 = qb*128 + w*16 + (lane >> 2);
            int c0 = kb*64 + 2*(lane & 3);
            #pragma unroll
            for (int j = 0; j < 8; j++) {
                int cg = c0 + j*8;
                if (cg     > r0)     s[j][0] = -1e30f;
                if (cg + 1 > r0)     s[j][1] = -1e30f;
                if (cg     > r0 + 8) s[j][2] = -1e30f;
                if (cg + 1 > r0 + 8) s[j][3] = -1e30f;
            }
        }

        // ---- online softmax ----
        float mx0 = -1e30f, mx1 = -1e30f;
        #pragma unroll
        for (int j = 0; j < 8; j++) {
            mx0 = fmaxf(mx0, fmaxf(s[j][0], s[j][1]));
            mx1 = fmaxf(mx1, fmaxf(s[j][2], s[j][3]));
        }
        mx0 = fmaxf(mx0, __shfl_xor_sync(0xffffffffu, mx0, 1));
        mx0 = fmaxf(mx0, __shfl_xor_sync(0xffffffffu, mx0, 2));
        mx1 = fmaxf(mx1, __shfl_xor_sync(0xffffffffu, mx1, 1));
        mx1 = fmaxf(mx1, __shfl_xor_sync(0xffffffffu, mx1, 2));
        float mn0 = fmaxf(m0, mx0), mn1 = fmaxf(m1, mx1);
        float cf0 = __expf(m0 - mn0), cf1 = __expf(m1 - mn1);
        m0 = mn0; m1 = mn1;
        float rs0 = 0.f, rs1 = 0.f;
        #pragma unroll
        for (int j = 0; j < 8; j++) {
            s[j][0] = __expf(s[j][0] - mn0); rs0 += s[j][0];
            s[j][1] = __expf(s[j][1] - mn0); rs0 += s[j][1];
            s[j][2] = __expf(s[j][2] - mn1); rs1 += s[j][2];
            s[j][3] = __expf(s[j][3] - mn1); rs1 += s[j][3];
        }
        rs0 += __shfl_xor_sync(0xffffffffu, rs0, 1);
        rs0 += __shfl_xor_sync(0xffffffffu, rs0, 2);
        rs1 += __shfl_xor_sync(0xffffffffu, rs1, 1);
        rs1 += __shfl_xor_sync(0xffffffffu, rs1, 2);
        l0 = l0*cf0 + rs0;
        l1 = l1*cf1 + rs1;
        #pragma unroll
        for (int j = 0; j < 8; j++) {
            o[j][0] *= cf0; o[j][1] *= cf0;
            o[j][2] *= cf1; o[j][3] *= cf1;
        }

        // ---- O += P V: 2-pass (p_hi + p_lo) * v_hi; V via ldmatrix.trans ----
        #pragma unroll
        for (int kk = 0; kk < 4; kk++) {
            uint32_t phi[4], plo[4];
            split2h(s[2*kk][0],   s[2*kk][1],   phi[0], plo[0]);
            split2h(s[2*kk][2],   s[2*kk][3],   phi[1], plo[1]);
            split2h(s[2*kk+1][0], s[2*kk+1][1], phi[2], plo[2]);
            split2h(s[2*kk+1][2], s[2*kk+1][3], phi[3], plo[3]);
            uint32_t vbh[4][4];
            #pragma unroll
            for (int j2 = 0; j2 < 4; j2++) {
                int vrow = kk*16 + ((mi & 1) << 3) + lr;                 // kv index
                uint32_t boff = (uint32_t)(vrow*AT_STRIDE +
                                           (j2*16 + ((mi >> 1) << 3))*2); // d col bytes
                ldsm4t(vbh[j2], sb + 1*STG_K + boff);
            }
            #pragma unroll
            for (int p = 0; p < 2; p++)
                #pragma unroll
                for (int j = 0; j < 8; j++)
                    mma_f16(o[j], (p == 0) ? phi : plo,
                            &vbh[j >> 1][(j & 1)*2]);
        }
        __syncthreads();   // all warps done reading stage kb&1 before refill
    }

    // ---- normalize + write (B,S,D) as fp16 hi/lo for oproj ----
    const int b = bh >> 4, h = bh & 15;
    const int s0 = qb*128 + w*16 + (lane >> 2);
    float i0 = 1.f / l0, i1 = 1.f / l1;
    #pragma unroll
    for (int j = 0; j < 8; j++) {
        int c = h*HDIM + j*8 + 2*(lane & 3);
        uint32_t hw, lw;
        size_t idx0 = ((size_t)b*SEQ + s0)*DMODEL + c;
        split2h(o[j][0]*i0, o[j][1]*i0, hw, lw);
        *(uint32_t*)&g_ah[idx0] = hw;
        *(uint32_t*)&g_al[idx0] = lw;
        size_t idx1 = ((size_t)b*SEQ + s0 + 8)*DMODEL + c;
        split2h(o[j][2]*i1, o[j][3]*i1, hw, lw);
        *(uint32_t*)&g_ah[idx1] = hw;
        *(uint32_t*)&g_al[idx1] = lw;
    }
}

// ---------------- launch ----------------
extern "C" void kernel_launch(void* const* d_in, const int* in_sizes, int n_in,
                              void* d_out, int out_size) {
    (void)in_sizes; (void)n_in; (void)out_size;
    const float* x  = (const float*)d_in[0];
    const float* wq = (const float*)d_in[1];
    const float* wk = (const float*)d_in[2];
    const float* wv = (const float*)d_in[3];
    const float* wo = (const float*)d_in[4];
    float* out = (float*)d_out;

    static bool attr_set = false;
    if (!attr_set) {
        cudaFuncSetAttribute(qkv_mma_kernel,  cudaFuncAttributeMaxDynamicSharedMemorySize, GEMM_SMEM);
        cudaFuncSetAttribute(oproj_mma_kernel, cudaFuncAttributeMaxDynamicSharedMemorySize, GEMM_SMEM);
        cudaFuncSetAttribute(attn_mma_kernel, cudaFuncAttributeMaxDynamicSharedMemorySize, ATTN_MMA_SMEM);
        attr_set = true;
    }

    presplit_kernel<<<dim3(NELEM/1024, 5), 256>>>(x, wq, wk, wv, wo);
    rope_table_kernel<<<SEQ*32/256, 256>>>();
    qkv_mma_kernel<<<dim3(8, 32, 3), 256, GEMM_SMEM>>>();
    attn_mma_kernel<<<dim3(16, 32), 256, ATTN_MMA_SMEM>>>();
    oproj_mma_kernel<<<dim3(8, 32), 256, GEMM_SMEM>>>(out);
}

// round 16
// speedup vs baseline: 1.5604x; 1.1331x over previous
#include <cuda_runtime.h>
#include <cuda_fp16.h>
#include <math.h>
#include <stdint.h>

#define DMODEL 1024
#define NHEADS 16
#define HDIM   64
#define BATCH  2
#define SEQ    2048
#define NELEM  (BATCH*SEQ*DMODEL)     // 4M
#define WELEM  (DMODEL*DMODEL)        // 1M

// ---------------- scratch (device globals; no allocation) ----------------
__device__ __half g_xh[NELEM], g_xl[NELEM];      // x hi/lo
__device__ __half g_wh[4*WELEM];                 // wq,wk,wv,wo hi only
__device__ __half g_qh[NELEM];                   // q (B,H,S,d) hi only, pre-scaled 1/8
__device__ __half g_kh[NELEM];                   // k hi only
__device__ __half g_vh[NELEM];                   // v hi only
__device__ __half g_ah[NELEM], g_al[NELEM];      // attn out (B,S,D) hi/lo
__device__ float g_rope[SEQ*32*2];               // [ss][f] -> (cos,sin)

// ---------------- helpers ----------------
__device__ __forceinline__ uint32_t smem_u32(const void* p) {
    uint32_t a;
    asm("{ .reg .u64 t; cvta.to.shared.u64 t, %1; cvt.u32.u64 %0, t; }" : "=r"(a) : "l"(p));
    return a;
}
__device__ __forceinline__ void ldsm4(uint32_t* r, uint32_t addr) {
    asm volatile("ldmatrix.sync.aligned.m8n8.x4.shared.b16 {%0,%1,%2,%3}, [%4];"
                 : "=r"(r[0]), "=r"(r[1]), "=r"(r[2]), "=r"(r[3]) : "r"(addr));
}
__device__ __forceinline__ void ldsm4t(uint32_t* r, uint32_t addr) {
    asm volatile("ldmatrix.sync.aligned.m8n8.x4.trans.shared.b16 {%0,%1,%2,%3}, [%4];"
                 : "=r"(r[0]), "=r"(r[1]), "=r"(r[2]), "=r"(r[3]) : "r"(addr));
}
__device__ __forceinline__ void mma_f16(float* d, const uint32_t* a, const uint32_t* b) {
    asm("mma.sync.aligned.m16n8k16.row.col.f32.f16.f16.f32 "
        "{%0,%1,%2,%3}, {%4,%5,%6,%7}, {%8,%9}, {%0,%1,%2,%3};"
        : "+f"(d[0]), "+f"(d[1]), "+f"(d[2]), "+f"(d[3])
        : "r"(a[0]), "r"(a[1]), "r"(a[2]), "r"(a[3]), "r"(b[0]), "r"(b[1]));
}
__device__ __forceinline__ void split2h(float a, float b, uint32_t& hi, uint32_t& lo) {
    __half2 h = __floats2half2_rn(a, b);
    hi = *(const uint32_t*)&h;
    __half2 l = __floats2half2_rn(a - __half2float(h.x), b - __half2float(h.y));
    lo = *(const uint32_t*)&l;
}
__device__ __forceinline__ uint32_t pack2h(float a, float b) {
    __half2 h = __floats2half2_rn(a, b);
    return *(const uint32_t*)&h;
}
__device__ __forceinline__ void cp16(uint32_t dst, const void* src) {
    asm volatile("cp.async.cg.shared.global [%0], [%1], 16;" :: "r"(dst), "l"(src));
}
#define CP_COMMIT() asm volatile("cp.async.commit_group;" ::: "memory")
#define CP_WAIT1()  asm volatile("cp.async.wait_group 1;" ::: "memory")
#define CP_WAIT0()  asm volatile("cp.async.wait_group 0;" ::: "memory")

// ---------------- kernel P: pre-split ----------------
__global__ void __launch_bounds__(256) presplit_kernel(
    const float* __restrict__ x,  const float* __restrict__ wq,
    const float* __restrict__ wk, const float* __restrict__ wv,
    const float* __restrict__ wo) {
    const int zz = blockIdx.y;
    int i = (blockIdx.x*256 + threadIdx.x)*4;
    if (zz == 0) {
        if (i >= NELEM) return;
        float4 v = *(const float4*)(x + i);
        uint32_t h0, l0, h1, l1;
        split2h(v.x, v.y, h0, l0);
        split2h(v.z, v.w, h1, l1);
        *(uint32_t*)&g_xh[i] = h0; *(uint32_t*)&g_xh[i+2] = h1;
        *(uint32_t*)&g_xl[i] = l0; *(uint32_t*)&g_xl[i+2] = l1;
    } else {
        if (i >= WELEM) return;
        const float* src = (zz==1)?wq:(zz==2)?wk:(zz==3)?wv:wo;
        float4 v = *(const float4*)(src + i);
        __half* dh = g_wh + (zz-1)*WELEM;
        *(uint32_t*)&dh[i]   = pack2h(v.x, v.y);
        *(uint32_t*)&dh[i+2] = pack2h(v.z, v.w);
    }
}

// ---------------- fp16 split-2 GEMM: cp.async double-buffered ----------------
#define SROW   80
#define SBUF   (128*SROW)          // 10240
#define STAGE  (3*SBUF)            // 30720
#define GEMM_SMEM (2*STAGE)        // 61440

__device__ __forceinline__ void gemm_ps(const __half* __restrict__ Ah,
                                        const __half* __restrict__ Al,
                                        const __half* __restrict__ Bh,
                                        float (&d)[4][4][4]) {
    extern __shared__ __align__(16) char dsm[];
    const uint32_t sbase = smem_u32(dsm);
    const int tid  = threadIdx.x;
    const int lane = tid & 31, wid = tid >> 5;
    const int wm = wid & 1, wn = wid >> 1;
    const int r = tid >> 1, half = tid & 1;
    const int mi = lane >> 3, lr = lane & 7;

    #pragma unroll
    for (int i = 0; i < 4; i++)
        #pragma unroll
        for (int j = 0; j < 4; j++)
            #pragma unroll
            for (int q = 0; q < 4; q++) d[i][j][q] = 0.f;

    const __half* pah = Ah + r*DMODEL + half*16;
    const __half* pal = Al + r*DMODEL + half*16;
    const __half* pbh = Bh + r*DMODEL + half*16;
    const uint32_t dbase = sbase + r*SROW + half*32;

    const int NCH = DMODEL / 32;

    {
        cp16(dbase + 0*SBUF, pah);  cp16(dbase + 0*SBUF + 16, pah + 8);
        cp16(dbase + 1*SBUF, pal);  cp16(dbase + 1*SBUF + 16, pal + 8);
        cp16(dbase + 2*SBUF, pbh);  cp16(dbase + 2*SBUF + 16, pbh + 8);
        CP_COMMIT();
    }

    for (int ch = 0; ch < NCH; ch++) {
        if (ch + 1 < NCH) {
            const uint32_t db = dbase + ((ch+1) & 1)*STAGE;
            const int ko = (ch+1)*32;
            cp16(db + 0*SBUF, pah + ko);  cp16(db + 0*SBUF + 16, pah + ko + 8);
            cp16(db + 1*SBUF, pal + ko);  cp16(db + 1*SBUF + 16, pal + ko + 8);
            cp16(db + 2*SBUF, pbh + ko);  cp16(db + 2*SBUF + 16, pbh + ko + 8);
            CP_COMMIT();
            CP_WAIT1();
        } else {
            CP_WAIT0();
        }
        __syncthreads();

        const uint32_t sb = sbase + (ch & 1)*STAGE;
        #pragma unroll
        for (int st = 0; st < 2; st++) {
            uint32_t ahi[4][4], alo[4][4];
            #pragma unroll
            for (int i = 0; i < 4; i++) {
                int arow = wm*64 + i*16 + ((mi & 1) << 3) + lr;
                uint32_t aoff = (uint32_t)(arow*SROW + st*32 + ((mi >> 1) << 4));
                ldsm4(ahi[i], sb + 0*SBUF + aoff);
                ldsm4(alo[i], sb + 1*SBUF + aoff);
            }
            uint32_t bhi[2][4];
            #pragma unroll
            for (int j2 = 0; j2 < 2; j2++) {
                int nrow = wn*32 + j2*16 + ((mi >> 1) << 3) + lr;
                uint32_t boff = (uint32_t)(nrow*SROW + st*32 + ((mi & 1) << 4));
                ldsm4(bhi[j2], sb + 2*SBUF + boff);
            }
            #pragma unroll
            for (int p = 0; p < 2; p++)
                #pragma unroll
                for (int i = 0; i < 4; i++)
                    #pragma unroll
                    for (int j = 0; j < 4; j++)
                        mma_f16(d[i][j], (p == 0) ? ahi[i] : alo[i],
                                &bhi[j >> 1][(j & 1)*2]);
        }
        __syncthreads();
    }
}

// ---------------- kernel 0: RoPE cos/sin table ----------------
__global__ void __launch_bounds__(256) rope_table_kernel() {
    int t = blockIdx.x * 256 + threadIdx.x;
    int f = t & 31, ss = t >> 5;
    const double lc = -0.28782313662425575;   // -ln(10000)/32
    float inv = (float)exp((double)f * lc);
    float ang = (float)ss * inv;
    double a = (double)ang;
    ((float2*)g_rope)[t] = make_float2((float)cos(a), (float)sin(a));
}

// ---------------- kernel 1: QKV projection + RoPE ----------------
__global__ void __launch_bounds__(256, 2) qkv_mma_kernel() {
    const int z  = blockIdx.z;
    const int m0 = blockIdx.y * 128;
    const int n0 = blockIdx.x * 128;

    float d[4][4][4];
    gemm_ps(g_xh + (size_t)m0*DMODEL, g_xl + (size_t)m0*DMODEL,
            g_wh + (size_t)z*WELEM + (size_t)n0*DMODEL, d);

    const int lane = threadIdx.x & 31, wid = threadIdx.x >> 5;
    const int wm = wid & 1, wn = wid >> 1;

    #pragma unroll
    for (int i = 0; i < 4; i++) {
        #pragma unroll
        for (int rr = 0; rr < 2; rr++) {
            int m  = m0 + wm*64 + i*16 + rr*8 + (lane >> 2);
            int ss = m & (SEQ - 1), bb = m >> 11;
            #pragma unroll
            for (int j = 0; j < 4; j++) {
                int c = n0 + wn*32 + j*8 + 2*(lane & 3);
                float e = d[i][j][rr*2 + 0];
                float o = d[i][j][rr*2 + 1];
                if (z < 2) {
                    float2 t = ((const float2*)g_rope)[ss*32 + ((c & 63) >> 1)];
                    float e2 = e*t.x - o*t.y;
                    o = e*t.y + o*t.x;
                    e = e2;
                }
                if (z == 0) { e *= 0.125f; o *= 0.125f; }   // fold 1/sqrt(64), exact
                int head = c >> 6, jd = c & 63;
                size_t idx = (((size_t)(bb*NHEADS + head))*SEQ + ss)*HDIM + jd;
                __half* dst = (z == 0) ? g_qh : (z == 1) ? g_kh : g_vh;
                *(uint32_t*)&dst[idx] = pack2h(e, o);
            }
        }
    }
}

// ---------------- kernel 3: output projection ----------------
__global__ void __launch_bounds__(256, 2) oproj_mma_kernel(float* __restrict__ out) {
    const int m0 = blockIdx.y * 128;
    const int n0 = blockIdx.x * 128;
    float d[4][4][4];
    gemm_ps(g_ah + (size_t)m0*DMODEL, g_al + (size_t)m0*DMODEL,
            g_wh + (size_t)3*WELEM + (size_t)n0*DMODEL, d);

    const int lane = threadIdx.x & 31, wid = threadIdx.x >> 5;
    const int wm = wid & 1, wn = wid >> 1;
    #pragma unroll
    for (int i = 0; i < 4; i++)
        #pragma unroll
        for (int rr = 0; rr < 2; rr++) {
            int m = m0 + wm*64 + i*16 + rr*8 + (lane >> 2);
            #pragma unroll
            for (int j = 0; j < 4; j++) {
                int c = n0 + wn*32 + j*8 + 2*(lane & 3);
                *(float2*)&out[(size_t)m*DMODEL + c] =
                    make_float2(d[i][j][rr*2 + 0], d[i][j][rr*2 + 1]);
            }
        }
}

// ---------------- kernel 2: causal flash attention (fp16 single-pass mma) -----------
// Q hi-only in registers; K/V hi-only, cp.async double-buffered; 2 CTAs/SM.
#define AT_STRIDE 144
#define STG_K  (64*AT_STRIDE)             // 9216 per buffer (KHI, VHI)
#define STG_SZ (2*STG_K)                  // 18432 per stage
#define SM_QHI 0                           // Q region == stage-0 region exactly
#define ATTN_MMA_SMEM (2*STG_SZ)           // 36864 B

__device__ __forceinline__ void attn_issue(uint32_t sb,
        const __half* kh, const __half* vh, int kb, int tid) {
    const int r = tid >> 2, q4 = tid & 3;
    const size_t g = (size_t)(kb*64 + r)*HDIM + q4*16;
    const uint32_t d = sb + r*AT_STRIDE + q4*32;
    cp16(d + 0*STG_K, kh + g); cp16(d + 0*STG_K + 16, kh + g + 8);
    cp16(d + 1*STG_K, vh + g); cp16(d + 1*STG_K + 16, vh + g + 8);
}

__global__ void __launch_bounds__(256, 2) attn_mma_kernel() {
    extern __shared__ __align__(16) char smc[];
    const uint32_t sbase = smem_u32(smc);
    const int tid = threadIdx.x, lane = tid & 31, w = tid >> 5;
    const int qb = (int)gridDim.x - 1 - (int)blockIdx.x;   // long blocks first
    const int bh = blockIdx.y;
    const int mi = lane >> 3, lr = lane & 7;

    const size_t hb = (size_t)bh*SEQ*HDIM;
    const __half* kh_g = g_kh + hb;
    const __half* vh_g = g_vh + hb;

    const int nkv = 2*(qb + 1);

    // ---- stage Q hi into the stage-0 region (prologue only) ----
    {
        int r = tid >> 1, half = tid & 1;
        const __half* qh = g_qh + hb + (size_t)(qb*128 + r)*HDIM + half*32;
        char* ph = smc + SM_QHI + r*AT_STRIDE + half*64;
        #pragma unroll
        for (int q = 0; q < 4; q++)
            *(uint4*)(ph + q*16) = *(const uint4*)(qh + q*8);
    }
    __syncthreads();

    // ---- hoist Q A-fragments ----
    uint32_t qhi[4][4];
    {
        int arow = w*16 + ((mi & 1) << 3) + lr;
        #pragma unroll
        for (int kk = 0; kk < 4; kk++) {
            uint32_t aoff = (uint32_t)(arow*AT_STRIDE + kk*32 + ((mi >> 1) << 4));
            ldsm4(qhi[kk], sbase + SM_QHI + aoff);
        }
    }
    __syncthreads();   // all warps done with Q smem before stage reuse

    // prefetch kv block 0 into stage 0
    attn_issue(sbase, kh_g, vh_g, 0, tid);
    CP_COMMIT();

    float o[8][4];
    #pragma unroll
    for (int j = 0; j < 8; j++) { o[j][0]=o[j][1]=o[j][2]=o[j][3]=0.f; }
    float m0 = -INFINITY, m1 = -INFINITY, l0 = 0.f, l1 = 0.f;

    for (int kb = 0; kb < nkv; kb++) {
        if (kb + 1 < nkv) {
            attn_issue(sbase + ((kb+1) & 1)*STG_SZ, kh_g, vh_g, kb + 1, tid);
            CP_COMMIT();
            CP_WAIT1();
        } else {
            CP_WAIT0();
        }
        __syncthreads();

        const uint32_t sb = sbase + (kb & 1)*STG_SZ;

        // ---- S = (Q/8) K^T, single pass hi*hi ----
        float s[8][4];
        #pragma unroll
        for (int j = 0; j < 8; j++) { s[j][0]=s[j][1]=s[j][2]=s[j][3]=0.f; }
        #pragma unroll
        for (int kk = 0; kk < 4; kk++) {
            uint32_t kbh[4][4];
            #pragma unroll
            for (int j2 = 0; j2 < 4; j2++) {
                int nrow = j2*16 + ((mi >> 1) << 3) + lr;
                uint32_t boff = (uint32_t)(nrow*AT_STRIDE + kk*32 + ((mi & 1) << 4));
                ldsm4(kbh[j2], sb + 0*STG_K + boff);
            }
            #pragma unroll
            for (int j = 0; j < 8; j++)
                mma_f16(s[j], qhi[kk], &kbh[j >> 1][(j & 1)*2]);
        }

        // ---- causal mask (diagonal band only) ----
        if (kb >= 2*qb) {
            int r0 = qb*128 + w*16 + (lane >> 2);
            int c0 = kb*64 + 2*(lane & 3);
            #pragma unroll
            for (int j = 0; j < 8; j++) {
                int cg = c0 + j*8;
                if (cg     > r0)     s[j][0] = -1e30f;
                if (cg + 1 > r0)     s[j][1] = -1e30f;
                if (cg     > r0 + 8) s[j][2] = -1e30f;
                if (cg + 1 > r0 + 8) s[j][3] = -1e30f;
            }
        }

        // ---- online softmax ----
        float mx0 = -1e30f, mx1 = -1e30f;
        #pragma unroll
        for (int j = 0; j < 8; j++) {
            mx0 = fmaxf(mx0, fmaxf(s[j][0], s[j][1]));
            mx1 = fmaxf(mx1, fmaxf(s[j][2], s[j][3]));
        }
        mx0 = fmaxf(mx0, __shfl_xor_sync(0xffffffffu, mx0, 1));
        mx0 = fmaxf(mx0, __shfl_xor_sync(0xffffffffu, mx0, 2));
        mx1 = fmaxf(mx1, __shfl_xor_sync(0xffffffffu, mx1, 1));
        mx1 = fmaxf(mx1, __shfl_xor_sync(0xffffffffu, mx1, 2));
        float mn0 = fmaxf(m0, mx0), mn1 = fmaxf(m1, mx1);
        float cf0 = __expf(m0 - mn0), cf1 = __expf(m1 - mn1);
        m0 = mn0; m1 = mn1;
        float rs0 = 0.f, rs1 = 0.f;
        #pragma unroll
        for (int j = 0; j < 8; j++) {
            s[j][0] = __expf(s[j][0] - mn0); rs0 += s[j][0];
            s[j][1] = __expf(s[j][1] - mn0); rs0 += s[j][1];
            s[j][2] = __expf(s[j][2] - mn1); rs1 += s[j][2];
            s[j][3] = __expf(s[j][3] - mn1); rs1 += s[j][3];
        }
        rs0 += __shfl_xor_sync(0xffffffffu, rs0, 1);
        rs0 += __shfl_xor_sync(0xffffffffu, rs0, 2);
        rs1 += __shfl_xor_sync(0xffffffffu, rs1, 1);
        rs1 += __shfl_xor_sync(0xffffffffu, rs1, 2);
        l0 = l0*cf0 + rs0;
        l1 = l1*cf1 + rs1;
        #pragma unroll
        for (int j = 0; j < 8; j++) {
            o[j][0] *= cf0; o[j][1] *= cf0;
            o[j][2] *= cf1; o[j][3] *= cf1;
        }

        // ---- O += P V, single pass; V via ldmatrix.trans ----
        #pragma unroll
        for (int kk = 0; kk < 4; kk++) {
            uint32_t phi[4];
            phi[0] = pack2h(s[2*kk][0],   s[2*kk][1]);
            phi[1] = pack2h(s[2*kk][2],   s[2*kk][3]);
            phi[2] = pack2h(s[2*kk+1][0], s[2*kk+1][1]);
            phi[3] = pack2h(s[2*kk+1][2], s[2*kk+1][3]);
            uint32_t vbh[4][4];
            #pragma unroll
            for (int j2 = 0; j2 < 4; j2++) {
                int vrow = kk*16 + ((mi & 1) << 3) + lr;                 // kv index
                uint32_t boff = (uint32_t)(vrow*AT_STRIDE +
                                           (j2*16 + ((mi >> 1) << 3))*2); // d col bytes
                ldsm4t(vbh[j2], sb + 1*STG_K + boff);
            }
            #pragma unroll
            for (int j = 0; j < 8; j++)
                mma_f16(o[j], phi, &vbh[j >> 1][(j & 1)*2]);
        }
        __syncthreads();   // all warps done reading stage kb&1 before refill
    }

    // ---- normalize + write (B,S,D) as fp16 hi/lo for oproj ----
    const int b = bh >> 4, h = bh & 15;
    const int s0 = qb*128 + w*16 + (lane >> 2);
    float i0 = 1.f / l0, i1 = 1.f / l1;
    #pragma unroll
    for (int j = 0; j < 8; j++) {
        int c = h*HDIM + j*8 + 2*(lane & 3);
        uint32_t hw, lw;
        size_t idx0 = ((size_t)b*SEQ + s0)*DMODEL + c;
        split2h(o[j][0]*i0, o[j][1]*i0, hw, lw);
        *(uint32_t*)&g_ah[idx0] = hw;
        *(uint32_t*)&g_al[idx0] = lw;
        size_t idx1 = ((size_t)b*SEQ + s0 + 8)*DMODEL + c;
        split2h(o[j][2]*i1, o[j][3]*i1, hw, lw);
        *(uint32_t*)&g_ah[idx1] = hw;
        *(uint32_t*)&g_al[idx1] = lw;
    }
}

// ---------------- launch ----------------
extern "C" void kernel_launch(void* const* d_in, const int* in_sizes, int n_in,
                              void* d_out, int out_size) {
    (void)in_sizes; (void)n_in; (void)out_size;
    const float* x  = (const float*)d_in[0];
    const float* wq = (const float*)d_in[1];
    const float* wk = (const float*)d_in[2];
    const float* wv = (const float*)d_in[3];
    const float* wo = (const float*)d_in[4];
    float* out = (float*)d_out;

    static bool attr_set = false;
    if (!attr_set) {
        cudaFuncSetAttribute(qkv_mma_kernel,  cudaFuncAttributeMaxDynamicSharedMemorySize, GEMM_SMEM);
        cudaFuncSetAttribute(oproj_mma_kernel, cudaFuncAttributeMaxDynamicSharedMemorySize, GEMM_SMEM);
        cudaFuncSetAttribute(attn_mma_kernel, cudaFuncAttributeMaxDynamicSharedMemorySize, ATTN_MMA_SMEM);
        attr_set = true;
    }

    presplit_kernel<<<dim3(NELEM/1024, 5), 256>>>(x, wq, wk, wv, wo);
    rope_table_kernel<<<SEQ*32/256, 256>>>();
    qkv_mma_kernel<<<dim3(8, 32, 3), 256, GEMM_SMEM>>>();
    attn_mma_kernel<<<dim3(16, 32), 256, ATTN_MMA_SMEM>>>();
    oproj_mma_kernel<<<dim3(8, 32), 256, GEMM_SMEM>>>(out);
}